// round 6
// baseline (speedup 1.0000x reference)
#include <cuda_runtime.h>
#include <cstdint>

#define NN   50000
#define EE   800000
#define FIN  128
#define HID  64
#define OUTC 64
#define NG   512

// ---------------- scratch (device globals; no runtime allocation) ----------------
__device__ __align__(16) float d_hW  [NN * HID];       // x @ W1
__device__ __align__(16) float d_deg [NN];
__device__ __align__(16) float d_dis [NN];
__device__ __align__(16) float d_acc1[NN * HID];       // GCN edge accumulator
__device__ __align__(16) float d_g1  [NN * HID];       // GCN output (relu)
__device__ __align__(16) float d_h2  [NN * 2 * HID];   // g1 @ W2  [N,2,64]
__device__ __align__(16) float d_als2[NN * 2];
__device__ __align__(16) float d_ald2[NN * 2];
__device__ __align__(16) float d_emax2[NN * 2];
__device__ __align__(16) float d_den2[NN * 2];
__device__ __align__(16) float d_acc2[NN * 2 * HID];
__device__ __align__(16) float d_g2  [NN * 2 * HID];   // GAT2 output (relu, concat)
__device__ __align__(16) float d_h3  [NN * OUTC];      // g2 @ W3
__device__ __align__(16) float d_als3[NN];
__device__ __align__(16) float d_ald3[NN];
__device__ __align__(16) float d_emax3[NN];
__device__ __align__(16) float d_den3[NN];
__device__ __align__(16) float d_acc3[NN * OUTC];
__device__ __align__(16) float d_pool[NG * OUTC];
__device__ __align__(16) float d_cnt [NG];

// canonical int32 index arrays (built from whatever width the harness provides)
__device__ int d_fmt;                 // 1 = input indices are int64, 0 = int32
__device__ int d_src[EE];
__device__ int d_dstA[EE];
__device__ int d_bat[NN];

// ---------------- helpers ----------------
__device__ __forceinline__ void atomic_add4(float* p, float4 v) {
    atomicAdd(p + 0, v.x);
    atomicAdd(p + 1, v.y);
    atomicAdd(p + 2, v.z);
    atomicAdd(p + 3, v.w);
}
__device__ __forceinline__ float4 scale4(float4 v, float s) {
    return make_float4(v.x * s, v.y * s, v.z * s, v.w * s);
}
__device__ __forceinline__ void atomicMaxFloat(float* addr, float value) {
    // order-preserving punning: non-negative floats -> int max, negative -> uint min
    if (value >= 0.f) atomicMax((int*)addr, __float_as_int(value));
    else              atomicMin((unsigned int*)addr, __float_as_uint(value));
}
__device__ __forceinline__ float lrelu(float x) { return x > 0.f ? x : 0.2f * x; }

// ---------------- index-width detection + canonicalization ----------------
__global__ void k_detect(const unsigned* __restrict__ ei_words) {
    // int64 node ids < 2^31: every odd 32-bit word is 0.
    // int32 data: odd words are random ids in [0, 50000) -> essentially never all zero.
    int is64 = 1;
    for (int i = 0; i < 256; i++) {
        if (ei_words[2 * i + 1] != 0u) { is64 = 0; break; }
    }
    d_fmt = is64;
}

__global__ void k_convert(const void* __restrict__ ei, const void* __restrict__ bat) {
    int i = blockIdx.x * blockDim.x + threadIdx.x;
    int fmt = d_fmt;
    if (i < EE) {
        if (fmt) {
            d_src [i] = (int)((const long long*)ei)[i];
            d_dstA[i] = (int)((const long long*)ei)[EE + i];
        } else {
            d_src [i] = ((const int*)ei)[i];
            d_dstA[i] = ((const int*)ei)[EE + i];
        }
    }
    if (i < NN) {
        d_bat[i] = fmt ? (int)((const long long*)bat)[i] : ((const int*)bat)[i];
    }
}

// ---------------- kernels ----------------
__global__ void k_zero() {
    unsigned i = blockIdx.x * blockDim.x + threadIdx.x;   // float4 index
    float4 z = make_float4(0.f, 0.f, 0.f, 0.f);
    if (i < NN * 128 / 4) ((float4*)d_acc2)[i] = z;
    if (i < NN * 64 / 4) { ((float4*)d_acc1)[i] = z; ((float4*)d_acc3)[i] = z; }
    if (i < NN * 2 / 4)   ((float4*)d_den2)[i] = z;
    if (i < NN / 4) { ((float4*)d_den3)[i] = z; ((float4*)d_deg)[i] = make_float4(1.f,1.f,1.f,1.f); }
    if (i < NG * 64 / 4)  ((float4*)d_pool)[i] = z;
    if (i < NG / 4)       ((float4*)d_cnt)[i] = z;
}

__global__ void k_deg() {
    int e = blockIdx.x * blockDim.x + threadIdx.x;
    if (e >= EE) return;
    atomicAdd(&d_deg[d_dstA[e]], 1.0f);
}

__global__ void k_dis() {
    int i = blockIdx.x * blockDim.x + threadIdx.x;
    if (i < NN) d_dis[i] = rsqrtf(d_deg[i]);
}

// C[n, MO] = A[n, K] @ W[K, MO]
template<int K, int MO, int ROWS>
__global__ void k_gemm(const float* __restrict__ A, const float* __restrict__ W,
                       float* __restrict__ C, int n) {
    __shared__ float Ws[K * MO];
    int tid = threadIdx.y * blockDim.x + threadIdx.x;
    for (int i = tid; i < K * MO; i += MO * ROWS) Ws[i] = W[i];
    __syncthreads();
    int node = blockIdx.x * ROWS + threadIdx.y;
    if (node >= n) return;
    int o = threadIdx.x;
    const float* a = A + (size_t)node * K;
    float sum = 0.f;
#pragma unroll
    for (int k = 0; k < K; k += 4) {
        float4 av = *(const float4*)(a + k);
        sum += av.x * Ws[(k + 0) * MO + o] + av.y * Ws[(k + 1) * MO + o]
             + av.z * Ws[(k + 2) * MO + o] + av.w * Ws[(k + 3) * MO + o];
    }
    C[(size_t)node * MO + o] = sum;
}

__global__ void k_gcnedge() {
    int e = blockIdx.x * 16 + (threadIdx.x >> 4);
    int q = threadIdx.x & 15;
    if (e >= EE) return;
    int s = d_src[e], d = d_dstA[e];
    float norm = d_dis[s] * d_dis[d];
    float4 v = ((const float4*)(d_hW + (size_t)s * 64))[q];
    atomic_add4(d_acc1 + (size_t)d * 64 + q * 4, scale4(v, norm));
}

__global__ void k_gcnfin(const float* __restrict__ b1) {
    int idx = blockIdx.x * blockDim.x + threadIdx.x;
    if (idx >= NN * 16) return;
    int n = idx >> 4, q = idx & 15;
    float sc = d_dis[n]; sc *= sc;
    float4 a  = ((const float4*)(d_acc1 + (size_t)n * 64))[q];
    float4 hv = ((const float4*)(d_hW  + (size_t)n * 64))[q];
    float4 b  = ((const float4*)b1)[q];
    float4 o = make_float4(fmaxf(a.x + hv.x * sc + b.x, 0.f),
                           fmaxf(a.y + hv.y * sc + b.y, 0.f),
                           fmaxf(a.z + hv.z * sc + b.z, 0.f),
                           fmaxf(a.w + hv.w * sc + b.w, 0.f));
    ((float4*)(d_g1 + (size_t)n * 64))[q] = o;
}

__global__ void k_al2(const float* __restrict__ asrc, const float* __restrict__ adst) {
    int n = blockIdx.x * 8 + (threadIdx.x >> 5);
    int lane = threadIdx.x & 31;
    if (n >= NN) return;
    const float* h = d_h2 + (size_t)n * 128;
    float s0 = h[lane] * asrc[lane]           + h[32 + lane] * asrc[32 + lane];
    float s1 = h[64 + lane] * asrc[64 + lane] + h[96 + lane] * asrc[96 + lane];
    float t0 = h[lane] * adst[lane]           + h[32 + lane] * adst[32 + lane];
    float t1 = h[64 + lane] * adst[64 + lane] + h[96 + lane] * adst[96 + lane];
#pragma unroll
    for (int off = 16; off; off >>= 1) {
        s0 += __shfl_xor_sync(~0u, s0, off);
        s1 += __shfl_xor_sync(~0u, s1, off);
        t0 += __shfl_xor_sync(~0u, t0, off);
        t1 += __shfl_xor_sync(~0u, t1, off);
    }
    if (lane == 0) {
        d_als2[n * 2] = s0; d_als2[n * 2 + 1] = s1;
        d_ald2[n * 2] = t0; d_ald2[n * 2 + 1] = t1;
        d_emax2[n * 2]     = lrelu(s0 + t0);   // self-loop seeds the max
        d_emax2[n * 2 + 1] = lrelu(s1 + t1);
    }
}

__global__ void k_gat2max() {
    int e = blockIdx.x * blockDim.x + threadIdx.x;
    if (e >= EE) return;
    int s = d_src[e], d = d_dstA[e];
#pragma unroll
    for (int h = 0; h < 2; h++) {
        float v = lrelu(d_als2[s * 2 + h] + d_ald2[d * 2 + h]);
        atomicMaxFloat(&d_emax2[d * 2 + h], v);
    }
}

__global__ void k_gat2edge() {
    int e = blockIdx.x * 8 + (threadIdx.x >> 5);
    int lane = threadIdx.x & 31;
    if (e >= EE) return;
    int s = d_src[e], d = d_dstA[e];
    int h = lane >> 4, q = lane & 15;
    float v = lrelu(d_als2[s * 2 + h] + d_ald2[d * 2 + h]);
    float ex = __expf(v - d_emax2[d * 2 + h]);
    if (q == 0) atomicAdd(&d_den2[d * 2 + h], ex);
    float4 val = ((const float4*)(d_h2 + (size_t)s * 128 + h * 64))[q];
    atomic_add4(d_acc2 + (size_t)d * 128 + h * 64 + q * 4, scale4(val, ex));
}

__global__ void k_gat2fin(const float* __restrict__ b2) {
    int idx = blockIdx.x * blockDim.x + threadIdx.x;
    if (idx >= NN * 32) return;
    int n = idx >> 5, q = idx & 31, h = q >> 4;
    float es  = lrelu(d_als2[n * 2 + h] + d_ald2[n * 2 + h]);
    float exs = __expf(es - d_emax2[n * 2 + h]);
    float inv = 1.f / (d_den2[n * 2 + h] + exs);
    float4 a  = ((const float4*)(d_acc2 + (size_t)n * 128))[q];
    float4 hv = ((const float4*)(d_h2  + (size_t)n * 128))[q];
    float4 b  = ((const float4*)b2)[q];
    float4 o = make_float4(fmaxf((a.x + exs * hv.x) * inv + b.x, 0.f),
                           fmaxf((a.y + exs * hv.y) * inv + b.y, 0.f),
                           fmaxf((a.z + exs * hv.z) * inv + b.z, 0.f),
                           fmaxf((a.w + exs * hv.w) * inv + b.w, 0.f));
    ((float4*)(d_g2 + (size_t)n * 128))[q] = o;
}

__global__ void k_al3(const float* __restrict__ asrc, const float* __restrict__ adst) {
    int n = blockIdx.x * 8 + (threadIdx.x >> 5);
    int lane = threadIdx.x & 31;
    if (n >= NN) return;
    const float* h = d_h3 + (size_t)n * 64;
    float s0 = h[lane] * asrc[lane] + h[32 + lane] * asrc[32 + lane];
    float t0 = h[lane] * adst[lane] + h[32 + lane] * adst[32 + lane];
#pragma unroll
    for (int off = 16; off; off >>= 1) {
        s0 += __shfl_xor_sync(~0u, s0, off);
        t0 += __shfl_xor_sync(~0u, t0, off);
    }
    if (lane == 0) {
        d_als3[n] = s0; d_ald3[n] = t0;
        d_emax3[n] = lrelu(s0 + t0);
    }
}

__global__ void k_gat3max() {
    int e = blockIdx.x * blockDim.x + threadIdx.x;
    if (e >= EE) return;
    int s = d_src[e], d = d_dstA[e];
    float v = lrelu(d_als3[s] + d_ald3[d]);
    atomicMaxFloat(&d_emax3[d], v);
}

__global__ void k_gat3edge() {
    int e = blockIdx.x * 16 + (threadIdx.x >> 4);
    int q = threadIdx.x & 15;
    if (e >= EE) return;
    int s = d_src[e], d = d_dstA[e];
    float v = lrelu(d_als3[s] + d_ald3[d]);
    float ex = __expf(v - d_emax3[d]);
    if (q == 0) atomicAdd(&d_den3[d], ex);
    float4 val = ((const float4*)(d_h3 + (size_t)s * 64))[q];
    atomic_add4(d_acc3 + (size_t)d * 64 + q * 4, scale4(val, ex));
}

__global__ void k_gat3finpool(const float* __restrict__ b3) {
    int idx = blockIdx.x * blockDim.x + threadIdx.x;
    if (idx >= NN * 16) return;
    int n = idx >> 4, q = idx & 15;
    float es  = lrelu(d_als3[n] + d_ald3[n]);
    float exs = __expf(es - d_emax3[n]);
    float inv = 1.f / (d_den3[n] + exs);
    float4 a  = ((const float4*)(d_acc3 + (size_t)n * 64))[q];
    float4 hv = ((const float4*)(d_h3  + (size_t)n * 64))[q];
    float4 b  = ((const float4*)b3)[q];
    float4 o = make_float4((a.x + exs * hv.x) * inv + b.x,
                           (a.y + exs * hv.y) * inv + b.y,
                           (a.z + exs * hv.z) * inv + b.z,
                           (a.w + exs * hv.w) * inv + b.w);
    int g = d_bat[n];
    atomic_add4(d_pool + (size_t)g * 64 + q * 4, o);
    if (q == 0) atomicAdd(&d_cnt[g], 1.0f);
}

__global__ void k_final(const float* __restrict__ Wfc, const float* __restrict__ bfc,
                        float* __restrict__ out) {
    int g = blockIdx.x * blockDim.x + threadIdx.x;
    if (g >= NG) return;
    float inv = 1.f / fmaxf(d_cnt[g], 1.f);
    float l0 = bfc[0], l1 = bfc[1];
#pragma unroll
    for (int f = 0; f < OUTC; f++) {
        float p = d_pool[g * OUTC + f] * inv;
        l0 += p * Wfc[f * 2 + 0];
        l1 += p * Wfc[f * 2 + 1];
    }
    float m = fmaxf(l0, l1);
    float lse = m + logf(expf(l0 - m) + expf(l1 - m));
    out[g * 2 + 0] = l0 - lse;
    out[g * 2 + 1] = l1 - lse;
}

// ---------------- host ----------------
extern "C" void kernel_launch(void* const* d_in, const int* in_sizes, int n_in,
                              void* d_out, int out_size) {
    const float* x    = (const float*)d_in[0];
    const void*  ei   = d_in[1];               // int32 or int64 — detected on device
    const void*  bat  = d_in[2];
    const float* W1   = (const float*)d_in[3];
    const float* b1   = (const float*)d_in[4];
    const float* W2   = (const float*)d_in[5];
    const float* as2  = (const float*)d_in[6];
    const float* ad2  = (const float*)d_in[7];
    const float* b2   = (const float*)d_in[8];
    const float* W3   = (const float*)d_in[9];
    const float* as3  = (const float*)d_in[10];
    const float* ad3  = (const float*)d_in[11];
    const float* b3   = (const float*)d_in[12];
    const float* Wfc  = (const float*)d_in[13];
    const float* bfc  = (const float*)d_in[14];
    float* out = (float*)d_out;

    void *p_hW, *p_g1, *p_g2, *p_h2, *p_h3;
    cudaGetSymbolAddress(&p_hW, d_hW);
    cudaGetSymbolAddress(&p_g1, d_g1);
    cudaGetSymbolAddress(&p_h2, d_h2);
    cudaGetSymbolAddress(&p_g2, d_g2);
    cudaGetSymbolAddress(&p_h3, d_h3);

    k_detect<<<1, 1>>>((const unsigned*)ei);
    k_convert<<<(EE + 255) / 256, 256>>>(ei, bat);
    k_zero<<<(NN * 128 / 4 + 255) / 256, 256>>>();
    k_deg<<<(EE + 255) / 256, 256>>>();
    k_dis<<<(NN + 255) / 256, 256>>>();

    // GCN
    k_gemm<128, 64, 4><<<(NN + 3) / 4, dim3(64, 4)>>>(x, W1, (float*)p_hW, NN);
    k_gcnedge<<<(EE + 15) / 16, 256>>>();
    k_gcnfin<<<(NN * 16 + 255) / 256, 256>>>(b1);

    // GAT layer 2 (2 heads, concat)
    k_gemm<64, 128, 2><<<(NN + 1) / 2, dim3(128, 2)>>>((const float*)p_g1, W2, (float*)p_h2, NN);
    k_al2<<<(NN + 7) / 8, 256>>>(as2, ad2);
    k_gat2max<<<(EE + 255) / 256, 256>>>();
    k_gat2edge<<<(EE + 7) / 8, 256>>>();
    k_gat2fin<<<(NN * 32 + 255) / 256, 256>>>(b2);

    // GAT layer 3 (1 head, no concat)
    k_gemm<128, 64, 4><<<(NN + 3) / 4, dim3(64, 4)>>>((const float*)p_g2, W3, (float*)p_h3, NN);
    k_al3<<<(NN + 7) / 8, 256>>>(as3, ad3);
    k_gat3max<<<(EE + 255) / 256, 256>>>();
    k_gat3edge<<<(EE + 15) / 16, 256>>>();
    k_gat3finpool<<<(NN * 16 + 255) / 256, 256>>>(b3);

    // pooled @ Wfc + log_softmax
    k_final<<<(NG + 255) / 256, 256>>>(Wfc, bfc, out);
}

// round 9
// speedup vs baseline: 1.4870x; 1.4870x over previous
#include <cuda_runtime.h>
#include <cstdint>

#define NN   50000
#define EE   800000
#define FIN  128
#define HID  64
#define OUTC 64
#define NG   512

// ---------------- scratch (device globals; no runtime allocation) ----------------
__device__ __align__(16) float d_hW  [NN * HID];       // x @ W1
__device__ __align__(16) float d_dis [NN];
__device__ __align__(16) float d_g1  [NN * HID];       // GCN output (relu)
__device__ __align__(16) float d_h2  [NN * 2 * HID];   // g1 @ W2  [N,2,64]
__device__ __align__(16) float d_als2[NN * 2];
__device__ __align__(16) float d_ald2[NN * 2];
__device__ __align__(16) float d_g2  [NN * 2 * HID];   // GAT2 output (relu, concat)
__device__ __align__(16) float d_h3  [NN * OUTC];      // g2 @ W3
__device__ __align__(16) float d_als3[NN];
__device__ __align__(16) float d_ald3[NN];
__device__ __align__(16) float d_pool[NG * OUTC];
__device__ __align__(16) float d_cnt [NG];

// canonical int32 indices + CSR (by destination)
__device__ int d_fmt;
__device__ int d_src [EE];
__device__ int d_dstA[EE];
__device__ int d_bat [NN];
__device__ int d_rowptr[NN + 1];
__device__ int d_cursor[NN];       // doubles as histogram counts
__device__ int d_csrc[EE];         // src ids grouped by dst

// ---------------- helpers ----------------
__device__ __forceinline__ float lrelu(float x) { return x > 0.f ? x : 0.2f * x; }
__device__ __forceinline__ float wmax(float v) {
#pragma unroll
    for (int off = 16; off; off >>= 1) v = fmaxf(v, __shfl_xor_sync(~0u, v, off));
    return v;
}

// ---------------- index-width detection + canonicalization ----------------
__global__ void k_detect(const unsigned* __restrict__ ei_words) {
    int is64 = 1;
    for (int i = 0; i < 256; i++)
        if (ei_words[2 * i + 1] != 0u) { is64 = 0; break; }
    d_fmt = is64;
}

__global__ void k_convert(const void* __restrict__ ei, const void* __restrict__ bat) {
    int i = blockIdx.x * blockDim.x + threadIdx.x;
    int fmt = d_fmt;
    if (i < EE) {
        if (fmt) {
            d_src [i] = (int)((const long long*)ei)[i];
            d_dstA[i] = (int)((const long long*)ei)[EE + i];
        } else {
            d_src [i] = ((const int*)ei)[i];
            d_dstA[i] = ((const int*)ei)[EE + i];
        }
    }
    if (i < NN) {
        d_bat[i] = fmt ? (int)((const long long*)bat)[i] : ((const int*)bat)[i];
        d_cursor[i] = 0;
    }
    if (i < NG) { d_cnt[i] = 0.f; }
    if (i < NG * OUTC / 4) ((float4*)d_pool)[i] = make_float4(0.f, 0.f, 0.f, 0.f);
}

__global__ void k_hist() {
    int e = blockIdx.x * blockDim.x + threadIdx.x;
    if (e < EE) atomicAdd(&d_cursor[d_dstA[e]], 1);
}

// single-block exclusive scan of counts -> rowptr; also zero cursor and compute dis
__global__ void k_scan() {
    const int T = 1024, CH = (NN + T - 1) / T;     // 49
    __shared__ int part[T];
    int t = threadIdx.x;
    int base = t * CH;
    int s = 0;
    for (int i = 0; i < CH; i++) {
        int n = base + i;
        if (n < NN) s += d_cursor[n];
    }
    part[t] = s;
    __syncthreads();
#pragma unroll
    for (int off = 1; off < T; off <<= 1) {
        int v = part[t];
        int add = (t >= off) ? part[t - off] : 0;
        __syncthreads();
        part[t] = v + add;
        __syncthreads();
    }
    int run = part[t] - s;    // exclusive prefix for this chunk
    for (int i = 0; i < CH; i++) {
        int n = base + i;
        if (n < NN) {
            int c = d_cursor[n];
            d_rowptr[n] = run;
            d_dis[n] = rsqrtf((float)(c + 1));     // +1 self loop
            d_cursor[n] = 0;
            run += c;
        }
    }
    if (t == 0) d_rowptr[NN] = EE;
}

__global__ void k_scatter() {
    int e = blockIdx.x * blockDim.x + threadIdx.x;
    if (e >= EE) return;
    int d = d_dstA[e];
    int slot = d_rowptr[d] + atomicAdd(&d_cursor[d], 1);
    d_csrc[slot] = d_src[e];
}

// ---------------- GEMM: C[n, MO] = A[n, K] @ W[K, MO] ----------------
template<int K, int MO, int ROWS>
__global__ void k_gemm(const float* __restrict__ A, const float* __restrict__ W,
                       float* __restrict__ C, int n) {
    __shared__ float Ws[K * MO];
    int tid = threadIdx.y * blockDim.x + threadIdx.x;
    for (int i = tid; i < K * MO; i += MO * ROWS) Ws[i] = W[i];
    __syncthreads();
    int node = blockIdx.x * ROWS + threadIdx.y;
    if (node >= n) return;
    int o = threadIdx.x;
    const float* a = A + (size_t)node * K;
    float sum = 0.f;
#pragma unroll
    for (int k = 0; k < K; k += 4) {
        float4 av = *(const float4*)(a + k);
        sum += av.x * Ws[(k + 0) * MO + o] + av.y * Ws[(k + 1) * MO + o]
             + av.z * Ws[(k + 2) * MO + o] + av.w * Ws[(k + 3) * MO + o];
    }
    C[(size_t)node * MO + o] = sum;
}

// ---------------- GCN: fused gather + norm + bias + relu ----------------
__global__ void k_gcn(const float* __restrict__ b1) {
    int n = blockIdx.x * 8 + (threadIdx.x >> 5);
    int lane = threadIdx.x & 31;
    if (n >= NN) return;
    int beg = d_rowptr[n], end = d_rowptr[n + 1];
    float a0 = 0.f, a1 = 0.f;
    for (int i = beg; i < end; i++) {
        int s = d_csrc[i];
        float w = d_dis[s];
        const float* h = d_hW + (size_t)s * 64;
        a0 += w * h[lane];
        a1 += w * h[32 + lane];
    }
    float dn = d_dis[n];
    const float* hn = d_hW + (size_t)n * 64;
    float o0 = fmaxf(dn * (a0 + dn * hn[lane])      + b1[lane],      0.f);
    float o1 = fmaxf(dn * (a1 + dn * hn[32 + lane]) + b1[32 + lane], 0.f);
    d_g1[(size_t)n * 64 + lane]      = o0;
    d_g1[(size_t)n * 64 + 32 + lane] = o1;
}

// ---------------- attention logits ----------------
__global__ void k_al2(const float* __restrict__ asrc, const float* __restrict__ adst) {
    int n = blockIdx.x * 8 + (threadIdx.x >> 5);
    int lane = threadIdx.x & 31;
    if (n >= NN) return;
    const float* h = d_h2 + (size_t)n * 128;
    float s0 = h[lane] * asrc[lane]           + h[32 + lane] * asrc[32 + lane];
    float s1 = h[64 + lane] * asrc[64 + lane] + h[96 + lane] * asrc[96 + lane];
    float t0 = h[lane] * adst[lane]           + h[32 + lane] * adst[32 + lane];
    float t1 = h[64 + lane] * adst[64 + lane] + h[96 + lane] * adst[96 + lane];
#pragma unroll
    for (int off = 16; off; off >>= 1) {
        s0 += __shfl_xor_sync(~0u, s0, off);
        s1 += __shfl_xor_sync(~0u, s1, off);
        t0 += __shfl_xor_sync(~0u, t0, off);
        t1 += __shfl_xor_sync(~0u, t1, off);
    }
    if (lane == 0) {
        d_als2[n * 2] = s0; d_als2[n * 2 + 1] = s1;
        d_ald2[n * 2] = t0; d_ald2[n * 2 + 1] = t1;
    }
}

__global__ void k_al3(const float* __restrict__ asrc, const float* __restrict__ adst) {
    int n = blockIdx.x * 8 + (threadIdx.x >> 5);
    int lane = threadIdx.x & 31;
    if (n >= NN) return;
    const float* h = d_h3 + (size_t)n * 64;
    float s0 = h[lane] * asrc[lane] + h[32 + lane] * asrc[32 + lane];
    float t0 = h[lane] * adst[lane] + h[32 + lane] * adst[32 + lane];
#pragma unroll
    for (int off = 16; off; off >>= 1) {
        s0 += __shfl_xor_sync(~0u, s0, off);
        t0 += __shfl_xor_sync(~0u, t0, off);
    }
    if (lane == 0) { d_als3[n] = s0; d_ald3[n] = t0; }
}

// ---------------- GAT2: fused softmax + aggregate + bias + relu ----------------
__global__ void k_gat2(const float* __restrict__ b2) {
    int n = blockIdx.x * 8 + (threadIdx.x >> 5);
    int lane = threadIdx.x & 31;
    if (n >= NN) return;
    int beg = d_rowptr[n], end = d_rowptr[n + 1];
    float2 ald = *(const float2*)(d_ald2 + n * 2);
    float2 als_self = *(const float2*)(d_als2 + n * 2);
    float e0s = lrelu(als_self.x + ald.x);
    float e1s = lrelu(als_self.y + ald.y);
    // pass A: max (edge-strided per lane, warp reduce)
    float m0 = e0s, m1 = e1s;
    for (int i = beg + lane; i < end; i += 32) {
        float2 a = *(const float2*)(d_als2 + d_csrc[i] * 2);
        m0 = fmaxf(m0, lrelu(a.x + ald.x));
        m1 = fmaxf(m1, lrelu(a.y + ald.y));
    }
    m0 = wmax(m0); m1 = wmax(m1);
    // pass B: accumulate
    float acc0 = 0.f, acc1 = 0.f, acc2 = 0.f, acc3 = 0.f;
    float den0 = 0.f, den1 = 0.f;
    for (int i = beg; i < end; i++) {
        int s = d_csrc[i];
        float2 a = *(const float2*)(d_als2 + s * 2);
        float x0 = __expf(lrelu(a.x + ald.x) - m0);
        float x1 = __expf(lrelu(a.y + ald.y) - m1);
        den0 += x0; den1 += x1;
        const float* h = d_h2 + (size_t)s * 128;
        acc0 += x0 * h[lane];
        acc1 += x0 * h[32 + lane];
        acc2 += x1 * h[64 + lane];
        acc3 += x1 * h[96 + lane];
    }
    // self loop
    {
        float x0 = __expf(e0s - m0), x1 = __expf(e1s - m1);
        den0 += x0; den1 += x1;
        const float* h = d_h2 + (size_t)n * 128;
        acc0 += x0 * h[lane];
        acc1 += x0 * h[32 + lane];
        acc2 += x1 * h[64 + lane];
        acc3 += x1 * h[96 + lane];
    }
    float i0 = 1.f / den0, i1 = 1.f / den1;
    float* g = d_g2 + (size_t)n * 128;
    g[lane]      = fmaxf(acc0 * i0 + b2[lane],      0.f);
    g[32 + lane] = fmaxf(acc1 * i0 + b2[32 + lane], 0.f);
    g[64 + lane] = fmaxf(acc2 * i1 + b2[64 + lane], 0.f);
    g[96 + lane] = fmaxf(acc3 * i1 + b2[96 + lane], 0.f);
}

// ---------------- GAT3: fused softmax + aggregate + bias + pool scatter ----------------
__global__ void k_gat3pool(const float* __restrict__ b3) {
    int n = blockIdx.x * 8 + (threadIdx.x >> 5);
    int lane = threadIdx.x & 31;
    if (n >= NN) return;
    int beg = d_rowptr[n], end = d_rowptr[n + 1];
    float ald = d_ald3[n];
    float es = lrelu(d_als3[n] + ald);
    float m = es;
    for (int i = beg + lane; i < end; i += 32)
        m = fmaxf(m, lrelu(d_als3[d_csrc[i]] + ald));
    m = wmax(m);
    float acc0 = 0.f, acc1 = 0.f, den = 0.f;
    for (int i = beg; i < end; i++) {
        int s = d_csrc[i];
        float x = __expf(lrelu(d_als3[s] + ald) - m);
        den += x;
        const float* h = d_h3 + (size_t)s * 64;
        acc0 += x * h[lane];
        acc1 += x * h[32 + lane];
    }
    {
        float x = __expf(es - m);
        den += x;
        const float* h = d_h3 + (size_t)n * 64;
        acc0 += x * h[lane];
        acc1 += x * h[32 + lane];
    }
    float inv = 1.f / den;
    float o0 = acc0 * inv + b3[lane];
    float o1 = acc1 * inv + b3[32 + lane];
    int g = d_bat[n];
    atomicAdd(&d_pool[(size_t)g * 64 + lane],      o0);
    atomicAdd(&d_pool[(size_t)g * 64 + 32 + lane], o1);
    if (lane == 0) atomicAdd(&d_cnt[g], 1.0f);
}

__global__ void k_final(const float* __restrict__ Wfc, const float* __restrict__ bfc,
                        float* __restrict__ out) {
    int g = blockIdx.x * blockDim.x + threadIdx.x;
    if (g >= NG) return;
    float inv = 1.f / fmaxf(d_cnt[g], 1.f);
    float l0 = bfc[0], l1 = bfc[1];
#pragma unroll
    for (int f = 0; f < OUTC; f++) {
        float p = d_pool[g * OUTC + f] * inv;
        l0 += p * Wfc[f * 2 + 0];
        l1 += p * Wfc[f * 2 + 1];
    }
    float m = fmaxf(l0, l1);
    float lse = m + logf(expf(l0 - m) + expf(l1 - m));
    out[g * 2 + 0] = l0 - lse;
    out[g * 2 + 1] = l1 - lse;
}

// ---------------- host ----------------
extern "C" void kernel_launch(void* const* d_in, const int* in_sizes, int n_in,
                              void* d_out, int out_size) {
    const float* x    = (const float*)d_in[0];
    const void*  ei   = d_in[1];
    const void*  bat  = d_in[2];
    const float* W1   = (const float*)d_in[3];
    const float* b1   = (const float*)d_in[4];
    const float* W2   = (const float*)d_in[5];
    const float* as2  = (const float*)d_in[6];
    const float* ad2  = (const float*)d_in[7];
    const float* b2   = (const float*)d_in[8];
    const float* W3   = (const float*)d_in[9];
    const float* as3  = (const float*)d_in[10];
    const float* ad3  = (const float*)d_in[11];
    const float* b3   = (const float*)d_in[12];
    const float* Wfc  = (const float*)d_in[13];
    const float* bfc  = (const float*)d_in[14];
    float* out = (float*)d_out;

    void *p_hW, *p_g1, *p_g2, *p_h2, *p_h3;
    cudaGetSymbolAddress(&p_hW, d_hW);
    cudaGetSymbolAddress(&p_g1, d_g1);
    cudaGetSymbolAddress(&p_h2, d_h2);
    cudaGetSymbolAddress(&p_g2, d_g2);
    cudaGetSymbolAddress(&p_h3, d_h3);

    // indices + CSR build
    k_detect<<<1, 1>>>((const unsigned*)ei);
    k_convert<<<(EE + 255) / 256, 256>>>(ei, bat);
    k_hist<<<(EE + 255) / 256, 256>>>();
    k_scan<<<1, 1024>>>();
    k_scatter<<<(EE + 255) / 256, 256>>>();

    // GCN
    k_gemm<128, 64, 4><<<(NN + 3) / 4, dim3(64, 4)>>>(x, W1, (float*)p_hW, NN);
    k_gcn<<<(NN + 7) / 8, 256>>>(b1);

    // GAT layer 2 (2 heads, concat)
    k_gemm<64, 128, 2><<<(NN + 1) / 2, dim3(128, 2)>>>((const float*)p_g1, W2, (float*)p_h2, NN);
    k_al2<<<(NN + 7) / 8, 256>>>(as2, ad2);
    k_gat2<<<(NN + 7) / 8, 256>>>(b2);

    // GAT layer 3 (1 head, mean over 1 head = identity)
    k_gemm<128, 64, 4><<<(NN + 3) / 4, dim3(64, 4)>>>((const float*)p_g2, W3, (float*)p_h3, NN);
    k_al3<<<(NN + 7) / 8, 256>>>(as3, ad3);
    k_gat3pool<<<(NN + 7) / 8, 256>>>(b3);

    // pooled @ Wfc + log_softmax
    k_final<<<(NG + 255) / 256, 256>>>(Wfc, bfc, out);
}

// round 11
// speedup vs baseline: 1.7084x; 1.1489x over previous
#include <cuda_runtime.h>
#include <cstdint>

#define NN   50000
#define EE   800000
#define FIN  128
#define HID  64
#define OUTC 64
#define NG   512

#define SCB  256                      // scan block size
#define NSB  ((NN + SCB - 1) / SCB)   // 196 scan blocks

// ---------------- scratch (device globals; no runtime allocation) ----------------
__device__ __align__(16) float d_hW  [NN * HID];       // x @ W1
__device__ __align__(16) float d_dis [NN];
__device__ __align__(16) float d_g1  [NN * HID];       // GCN output (relu)
__device__ __align__(16) float d_h2  [NN * 2 * HID];   // g1 @ W2  [N,2,64]
__device__ __align__(16) float d_als2[NN * 2];
__device__ __align__(16) float d_ald2[NN * 2];
__device__ __align__(16) float d_g2  [NN * 2 * HID];   // GAT2 output (relu, concat)
__device__ __align__(16) float d_h3  [NN * OUTC];      // g2 @ W3
__device__ __align__(16) float d_als3[NN];
__device__ __align__(16) float d_ald3[NN];
__device__ __align__(16) float d_pool[NG * OUTC];
__device__ __align__(16) float d_cnt [NG];

// canonical int32 indices + CSR (by destination)
__device__ int d_fmt;
__device__ int d_src [EE];
__device__ int d_dstA[EE];
__device__ int d_bat [NN];
__device__ int d_rowptr[NN + 1];
__device__ int d_cursor[NN];       // doubles as histogram counts
__device__ int d_csrc[EE];         // src ids grouped by dst
__device__ int d_part[NSB];        // per-block partial sums for the scan

// ---------------- helpers ----------------
__device__ __forceinline__ float lrelu(float x) { return x > 0.f ? x : 0.2f * x; }
__device__ __forceinline__ float wmax(float v) {
#pragma unroll
    for (int off = 16; off; off >>= 1) v = fmaxf(v, __shfl_xor_sync(~0u, v, off));
    return v;
}

// ---------------- index-width detection + canonicalization ----------------
__global__ void k_detect(const unsigned* __restrict__ ei_words) {
    // int64 ids < 2^31 -> every odd 32-bit word is 0; int32 data -> some odd word nonzero
    int t = threadIdx.x;
    unsigned v = 0;
#pragma unroll
    for (int i = 0; i < 8; i++) v |= ei_words[2 * (t + 32 * i) + 1];
    unsigned any = __ballot_sync(~0u, v != 0u);
    if (t == 0) d_fmt = (any == 0u) ? 1 : 0;
}

__global__ void k_convert(const void* __restrict__ ei, const void* __restrict__ bat) {
    int i = blockIdx.x * blockDim.x + threadIdx.x;
    int fmt = d_fmt;
    if (i < EE) {
        if (fmt) {
            d_src [i] = (int)((const long long*)ei)[i];
            d_dstA[i] = (int)((const long long*)ei)[EE + i];
        } else {
            d_src [i] = ((const int*)ei)[i];
            d_dstA[i] = ((const int*)ei)[EE + i];
        }
    }
    if (i < NN) {
        d_bat[i] = fmt ? (int)((const long long*)bat)[i] : ((const int*)bat)[i];
        d_cursor[i] = 0;
    }
    if (i < NG) { d_cnt[i] = 0.f; }
    if (i < NG * OUTC / 4) ((float4*)d_pool)[i] = make_float4(0.f, 0.f, 0.f, 0.f);
}

__global__ void k_hist() {
    int e = blockIdx.x * blockDim.x + threadIdx.x;
    if (e < EE) atomicAdd(&d_cursor[d_dstA[e]], 1);
}

// ---- parallel exclusive scan over d_cursor (3 phases) ----
__global__ void k_blocksum() {
    __shared__ int sh[SCB];
    int t = threadIdx.x, n = blockIdx.x * SCB + t;
    int c = (n < NN) ? d_cursor[n] : 0;
    sh[t] = c;
    __syncthreads();
#pragma unroll
    for (int off = SCB / 2; off; off >>= 1) {
        if (t < off) sh[t] += sh[t + off];
        __syncthreads();
    }
    if (t == 0) d_part[blockIdx.x] = sh[0];
}

__global__ void k_scanpart() {
    __shared__ int sh[SCB];
    int t = threadIdx.x;
    int v = (t < NSB) ? d_part[t] : 0;
    sh[t] = v;
    __syncthreads();
#pragma unroll
    for (int off = 1; off < SCB; off <<= 1) {
        int u = sh[t];
        int add = (t >= off) ? sh[t - off] : 0;
        __syncthreads();
        sh[t] = u + add;
        __syncthreads();
    }
    if (t < NSB) d_part[t] = sh[t] - v;   // exclusive
}

__global__ void k_rowptr() {
    __shared__ int sh[SCB];
    int t = threadIdx.x, n = blockIdx.x * SCB + t;
    int c = (n < NN) ? d_cursor[n] : 0;
    sh[t] = c;
    __syncthreads();
#pragma unroll
    for (int off = 1; off < SCB; off <<= 1) {
        int u = sh[t];
        int add = (t >= off) ? sh[t - off] : 0;
        __syncthreads();
        sh[t] = u + add;
        __syncthreads();
    }
    if (n < NN) {
        d_rowptr[n] = d_part[blockIdx.x] + sh[t] - c;   // exclusive prefix
        d_dis[n] = rsqrtf((float)(c + 1));              // +1 self loop
        d_cursor[n] = 0;
        if (n == NN - 1) d_rowptr[NN] = EE;
    }
}

__global__ void k_scatter() {
    int e = blockIdx.x * blockDim.x + threadIdx.x;
    if (e >= EE) return;
    int d = d_dstA[e];
    int slot = d_rowptr[d] + atomicAdd(&d_cursor[d], 1);
    d_csrc[slot] = d_src[e];
}

// ---------------- GEMM: C[n, MO] = A[n, K] @ W[K, MO] ----------------
template<int K, int MO, int ROWS>
__global__ void k_gemm(const float* __restrict__ A, const float* __restrict__ W,
                       float* __restrict__ C, int n) {
    __shared__ float Ws[K * MO];
    int tid = threadIdx.y * blockDim.x + threadIdx.x;
    for (int i = tid; i < K * MO; i += MO * ROWS) Ws[i] = W[i];
    __syncthreads();
    int node = blockIdx.x * ROWS + threadIdx.y;
    if (node >= n) return;
    int o = threadIdx.x;
    const float* a = A + (size_t)node * K;
    float sum = 0.f;
#pragma unroll
    for (int k = 0; k < K; k += 4) {
        float4 av = *(const float4*)(a + k);
        sum += av.x * Ws[(k + 0) * MO + o] + av.y * Ws[(k + 1) * MO + o]
             + av.z * Ws[(k + 2) * MO + o] + av.w * Ws[(k + 3) * MO + o];
    }
    C[(size_t)node * MO + o] = sum;
}

// ---------------- GCN: fused gather + norm + bias + relu ----------------
__global__ void k_gcn(const float* __restrict__ b1) {
    int n = blockIdx.x * 8 + (threadIdx.x >> 5);
    int lane = threadIdx.x & 31;
    if (n >= NN) return;
    int beg = d_rowptr[n], end = d_rowptr[n + 1];
    float a0 = 0.f, a1 = 0.f;
#pragma unroll 4
    for (int i = beg; i < end; i++) {
        int s = d_csrc[i];
        float w = d_dis[s];
        const float* h = d_hW + (size_t)s * 64;
        a0 += w * h[lane];
        a1 += w * h[32 + lane];
    }
    float dn = d_dis[n];
    const float* hn = d_hW + (size_t)n * 64;
    float o0 = fmaxf(dn * (a0 + dn * hn[lane])      + b1[lane],      0.f);
    float o1 = fmaxf(dn * (a1 + dn * hn[32 + lane]) + b1[32 + lane], 0.f);
    d_g1[(size_t)n * 64 + lane]      = o0;
    d_g1[(size_t)n * 64 + 32 + lane] = o1;
}

// ---------------- attention logits ----------------
__global__ void k_al2(const float* __restrict__ asrc, const float* __restrict__ adst) {
    int n = blockIdx.x * 8 + (threadIdx.x >> 5);
    int lane = threadIdx.x & 31;
    if (n >= NN) return;
    const float* h = d_h2 + (size_t)n * 128;
    float s0 = h[lane] * asrc[lane]           + h[32 + lane] * asrc[32 + lane];
    float s1 = h[64 + lane] * asrc[64 + lane] + h[96 + lane] * asrc[96 + lane];
    float t0 = h[lane] * adst[lane]           + h[32 + lane] * adst[32 + lane];
    float t1 = h[64 + lane] * adst[64 + lane] + h[96 + lane] * adst[96 + lane];
#pragma unroll
    for (int off = 16; off; off >>= 1) {
        s0 += __shfl_xor_sync(~0u, s0, off);
        s1 += __shfl_xor_sync(~0u, s1, off);
        t0 += __shfl_xor_sync(~0u, t0, off);
        t1 += __shfl_xor_sync(~0u, t1, off);
    }
    if (lane == 0) {
        d_als2[n * 2] = s0; d_als2[n * 2 + 1] = s1;
        d_ald2[n * 2] = t0; d_ald2[n * 2 + 1] = t1;
    }
}

__global__ void k_al3(const float* __restrict__ asrc, const float* __restrict__ adst) {
    int n = blockIdx.x * 8 + (threadIdx.x >> 5);
    int lane = threadIdx.x & 31;
    if (n >= NN) return;
    const float* h = d_h3 + (size_t)n * 64;
    float s0 = h[lane] * asrc[lane] + h[32 + lane] * asrc[32 + lane];
    float t0 = h[lane] * adst[lane] + h[32 + lane] * adst[32 + lane];
#pragma unroll
    for (int off = 16; off; off >>= 1) {
        s0 += __shfl_xor_sync(~0u, s0, off);
        t0 += __shfl_xor_sync(~0u, t0, off);
    }
    if (lane == 0) { d_als3[n] = s0; d_ald3[n] = t0; }
}

// ---------------- GAT2: fused softmax + aggregate + bias + relu ----------------
__global__ void k_gat2(const float* __restrict__ b2) {
    int n = blockIdx.x * 8 + (threadIdx.x >> 5);
    int lane = threadIdx.x & 31;
    if (n >= NN) return;
    int beg = d_rowptr[n], end = d_rowptr[n + 1];
    float2 ald = *(const float2*)(d_ald2 + n * 2);
    float2 als_self = *(const float2*)(d_als2 + n * 2);
    float e0s = lrelu(als_self.x + ald.x);
    float e1s = lrelu(als_self.y + ald.y);
    // pass A: max (edge-strided per lane, warp reduce)
    float m0 = e0s, m1 = e1s;
    for (int i = beg + lane; i < end; i += 32) {
        float2 a = *(const float2*)(d_als2 + d_csrc[i] * 2);
        m0 = fmaxf(m0, lrelu(a.x + ald.x));
        m1 = fmaxf(m1, lrelu(a.y + ald.y));
    }
    m0 = wmax(m0); m1 = wmax(m1);
    // pass B: accumulate
    float acc0 = 0.f, acc1 = 0.f, acc2 = 0.f, acc3 = 0.f;
    float den0 = 0.f, den1 = 0.f;
#pragma unroll 2
    for (int i = beg; i < end; i++) {
        int s = d_csrc[i];
        float2 a = *(const float2*)(d_als2 + s * 2);
        float x0 = __expf(lrelu(a.x + ald.x) - m0);
        float x1 = __expf(lrelu(a.y + ald.y) - m1);
        den0 += x0; den1 += x1;
        const float* h = d_h2 + (size_t)s * 128;
        acc0 += x0 * h[lane];
        acc1 += x0 * h[32 + lane];
        acc2 += x1 * h[64 + lane];
        acc3 += x1 * h[96 + lane];
    }
    // self loop
    {
        float x0 = __expf(e0s - m0), x1 = __expf(e1s - m1);
        den0 += x0; den1 += x1;
        const float* h = d_h2 + (size_t)n * 128;
        acc0 += x0 * h[lane];
        acc1 += x0 * h[32 + lane];
        acc2 += x1 * h[64 + lane];
        acc3 += x1 * h[96 + lane];
    }
    float i0 = 1.f / den0, i1 = 1.f / den1;
    float* g = d_g2 + (size_t)n * 128;
    g[lane]      = fmaxf(acc0 * i0 + b2[lane],      0.f);
    g[32 + lane] = fmaxf(acc1 * i0 + b2[32 + lane], 0.f);
    g[64 + lane] = fmaxf(acc2 * i1 + b2[64 + lane], 0.f);
    g[96 + lane] = fmaxf(acc3 * i1 + b2[96 + lane], 0.f);
}

// ---------------- GAT3: fused softmax + aggregate + bias + pool scatter ----------------
__global__ void k_gat3pool(const float* __restrict__ b3) {
    int n = blockIdx.x * 8 + (threadIdx.x >> 5);
    int lane = threadIdx.x & 31;
    if (n >= NN) return;
    int beg = d_rowptr[n], end = d_rowptr[n + 1];
    float ald = d_ald3[n];
    float es = lrelu(d_als3[n] + ald);
    float m = es;
    for (int i = beg + lane; i < end; i += 32)
        m = fmaxf(m, lrelu(d_als3[d_csrc[i]] + ald));
    m = wmax(m);
    float acc0 = 0.f, acc1 = 0.f, den = 0.f;
#pragma unroll 2
    for (int i = beg; i < end; i++) {
        int s = d_csrc[i];
        float x = __expf(lrelu(d_als3[s] + ald) - m);
        den += x;
        const float* h = d_h3 + (size_t)s * 64;
        acc0 += x * h[lane];
        acc1 += x * h[32 + lane];
    }
    {
        float x = __expf(es - m);
        den += x;
        const float* h = d_h3 + (size_t)n * 64;
        acc0 += x * h[lane];
        acc1 += x * h[32 + lane];
    }
    float inv = 1.f / den;
    float o0 = acc0 * inv + b3[lane];
    float o1 = acc1 * inv + b3[32 + lane];
    int g = d_bat[n];
    atomicAdd(&d_pool[(size_t)g * 64 + lane],      o0);
    atomicAdd(&d_pool[(size_t)g * 64 + 32 + lane], o1);
    if (lane == 0) atomicAdd(&d_cnt[g], 1.0f);
}

__global__ void k_final(const float* __restrict__ Wfc, const float* __restrict__ bfc,
                        float* __restrict__ out) {
    int g = blockIdx.x * blockDim.x + threadIdx.x;
    if (g >= NG) return;
    float inv = 1.f / fmaxf(d_cnt[g], 1.f);
    float l0 = bfc[0], l1 = bfc[1];
#pragma unroll
    for (int f = 0; f < OUTC; f++) {
        float p = d_pool[g * OUTC + f] * inv;
        l0 += p * Wfc[f * 2 + 0];
        l1 += p * Wfc[f * 2 + 1];
    }
    float m = fmaxf(l0, l1);
    float lse = m + logf(expf(l0 - m) + expf(l1 - m));
    out[g * 2 + 0] = l0 - lse;
    out[g * 2 + 1] = l1 - lse;
}

// ---------------- host ----------------
extern "C" void kernel_launch(void* const* d_in, const int* in_sizes, int n_in,
                              void* d_out, int out_size) {
    const float* x    = (const float*)d_in[0];
    const void*  ei   = d_in[1];
    const void*  bat  = d_in[2];
    const float* W1   = (const float*)d_in[3];
    const float* b1   = (const float*)d_in[4];
    const float* W2   = (const float*)d_in[5];
    const float* as2  = (const float*)d_in[6];
    const float* ad2  = (const float*)d_in[7];
    const float* b2   = (const float*)d_in[8];
    const float* W3   = (const float*)d_in[9];
    const float* as3  = (const float*)d_in[10];
    const float* ad3  = (const float*)d_in[11];
    const float* b3   = (const float*)d_in[12];
    const float* Wfc  = (const float*)d_in[13];
    const float* bfc  = (const float*)d_in[14];
    float* out = (float*)d_out;

    void *p_hW, *p_g1, *p_g2, *p_h2, *p_h3;
    cudaGetSymbolAddress(&p_hW, d_hW);
    cudaGetSymbolAddress(&p_g1, d_g1);
    cudaGetSymbolAddress(&p_h2, d_h2);
    cudaGetSymbolAddress(&p_g2, d_g2);
    cudaGetSymbolAddress(&p_h3, d_h3);

    // indices + CSR build
    k_detect<<<1, 32>>>((const unsigned*)ei);
    k_convert<<<(EE + 255) / 256, 256>>>(ei, bat);
    k_hist<<<(EE + 255) / 256, 256>>>();
    k_blocksum<<<NSB, SCB>>>();
    k_scanpart<<<1, SCB>>>();
    k_rowptr<<<NSB, SCB>>>();
    k_scatter<<<(EE + 255) / 256, 256>>>();

    // GCN
    k_gemm<128, 64, 4><<<(NN + 3) / 4, dim3(64, 4)>>>(x, W1, (float*)p_hW, NN);
    k_gcn<<<(NN + 7) / 8, 256>>>(b1);

    // GAT layer 2 (2 heads, concat)
    k_gemm<64, 128, 2><<<(NN + 1) / 2, dim3(128, 2)>>>((const float*)p_g1, W2, (float*)p_h2, NN);
    k_al2<<<(NN + 7) / 8, 256>>>(as2, ad2);
    k_gat2<<<(NN + 7) / 8, 256>>>(b2);

    // GAT layer 3 (1 head, mean over 1 head = identity)
    k_gemm<128, 64, 4><<<(NN + 3) / 4, dim3(64, 4)>>>((const float*)p_g2, W3, (float*)p_h3, NN);
    k_al3<<<(NN + 7) / 8, 256>>>(as3, ad3);
    k_gat3pool<<<(NN + 7) / 8, 256>>>(b3);

    // pooled @ Wfc + log_softmax
    k_final<<<(NG + 255) / 256, 256>>>(Wfc, bfc, out);
}

// round 13
// speedup vs baseline: 1.7447x; 1.0213x over previous
#include <cuda_runtime.h>
#include <cstdint>

#define NN   50000
#define EE   800000
#define FIN  128
#define HID  64
#define OUTC 64
#define NG   512

#define SCB  256                      // scan block size
#define NSB  ((NN + SCB - 1) / SCB)   // 196 scan blocks

// ---------------- scratch (device globals; no runtime allocation) ----------------
__device__ __align__(16) float d_hW  [NN * HID];       // x @ W1
__device__ __align__(16) float d_dis [NN];
__device__ __align__(16) float d_g1  [NN * HID];       // GCN output (relu)
__device__ __align__(16) float d_h2  [NN * 2 * HID];   // g1 @ W2  [N,2,64]
__device__ __align__(16) float d_als2[NN * 2];
__device__ __align__(16) float d_ald2[NN * 2];
__device__ __align__(16) float d_g2  [NN * 2 * HID];   // GAT2 output (relu, concat)
__device__ __align__(16) float d_h3  [NN * OUTC];      // g2 @ W3
__device__ __align__(16) float d_als3[NN];
__device__ __align__(16) float d_ald3[NN];
__device__ __align__(16) float d_pool[NG * OUTC];
__device__ __align__(16) float d_cnt [NG];

// canonical int32 indices + CSR (by destination)
__device__ int d_fmt;
__device__ int d_src [EE];
__device__ int d_dstA[EE];
__device__ int d_bat [NN];
__device__ int d_rowptr[NN + 1];
__device__ int d_cursor[NN];       // histogram counts / scatter cursor
__device__ int d_csrc[EE];         // src ids grouped by dst
__device__ int d_part[NSB];        // per-block partial sums for the scan

// ---------------- helpers ----------------
__device__ __forceinline__ float lrelu(float x) { return x > 0.f ? x : 0.2f * x; }
__device__ __forceinline__ float wmax(float v) {
#pragma unroll
    for (int off = 16; off; off >>= 1) v = fmaxf(v, __shfl_xor_sync(~0u, v, off));
    return v;
}
__device__ __forceinline__ float wsum(float v) {
#pragma unroll
    for (int off = 16; off; off >>= 1) v += __shfl_xor_sync(~0u, v, off);
    return v;
}

// ---------------- index-width detection + canonicalization ----------------
__global__ void k_detect(const unsigned* __restrict__ ei_words) {
    int t = threadIdx.x;
    unsigned v = 0;
#pragma unroll
    for (int i = 0; i < 8; i++) v |= ei_words[2 * (t + 32 * i) + 1];
    unsigned any = __ballot_sync(~0u, v != 0u);
    if (t == 0) d_fmt = (any == 0u) ? 1 : 0;
}

__global__ void k_zero0() {
    int i = blockIdx.x * blockDim.x + threadIdx.x;
    if (i < NN) d_cursor[i] = 0;
    if (i < NG) d_cnt[i] = 0.f;
    if (i < NG * OUTC / 4) ((float4*)d_pool)[i] = make_float4(0.f, 0.f, 0.f, 0.f);
}

// convert + fused degree histogram
__global__ void k_convert(const void* __restrict__ ei, const void* __restrict__ bat) {
    int i = blockIdx.x * blockDim.x + threadIdx.x;
    int fmt = d_fmt;
    if (i < EE) {
        int s, d;
        if (fmt) {
            s = (int)((const long long*)ei)[i];
            d = (int)((const long long*)ei)[EE + i];
        } else {
            s = ((const int*)ei)[i];
            d = ((const int*)ei)[EE + i];
        }
        d_src [i] = s;
        d_dstA[i] = d;
        atomicAdd(&d_cursor[d], 1);
    }
    if (i < NN)
        d_bat[i] = fmt ? (int)((const long long*)bat)[i] : ((const int*)bat)[i];
}

// ---- parallel exclusive scan over d_cursor (3 phases) ----
__global__ void k_blocksum() {
    __shared__ int sh[SCB];
    int t = threadIdx.x, n = blockIdx.x * SCB + t;
    int c = (n < NN) ? d_cursor[n] : 0;
    sh[t] = c;
    __syncthreads();
#pragma unroll
    for (int off = SCB / 2; off; off >>= 1) {
        if (t < off) sh[t] += sh[t + off];
        __syncthreads();
    }
    if (t == 0) d_part[blockIdx.x] = sh[0];
}

__global__ void k_scanpart() {
    __shared__ int sh[SCB];
    int t = threadIdx.x;
    int v = (t < NSB) ? d_part[t] : 0;
    sh[t] = v;
    __syncthreads();
#pragma unroll
    for (int off = 1; off < SCB; off <<= 1) {
        int u = sh[t];
        int add = (t >= off) ? sh[t - off] : 0;
        __syncthreads();
        sh[t] = u + add;
        __syncthreads();
    }
    if (t < NSB) d_part[t] = sh[t] - v;   // exclusive
}

__global__ void k_rowptr() {
    __shared__ int sh[SCB];
    int t = threadIdx.x, n = blockIdx.x * SCB + t;
    int c = (n < NN) ? d_cursor[n] : 0;
    sh[t] = c;
    __syncthreads();
#pragma unroll
    for (int off = 1; off < SCB; off <<= 1) {
        int u = sh[t];
        int add = (t >= off) ? sh[t - off] : 0;
        __syncthreads();
        sh[t] = u + add;
        __syncthreads();
    }
    if (n < NN) {
        d_rowptr[n] = d_part[blockIdx.x] + sh[t] - c;   // exclusive prefix
        d_dis[n] = rsqrtf((float)(c + 1));              // +1 self loop
        d_cursor[n] = 0;
        if (n == NN - 1) d_rowptr[NN] = EE;
    }
}

__global__ void k_scatter() {
    int e = blockIdx.x * blockDim.x + threadIdx.x;
    if (e >= EE) return;
    int d = d_dstA[e];
    int slot = d_rowptr[d] + atomicAdd(&d_cursor[d], 1);
    d_csrc[slot] = d_src[e];
}

// ---------------- GEMM: C[n, MO] = A[n, K] @ W[K, MO] ----------------
template<int K, int MO, int ROWS>
__global__ void k_gemm(const float* __restrict__ A, const float* __restrict__ W,
                       float* __restrict__ C, int n) {
    __shared__ float Ws[K * MO];
    int tid = threadIdx.y * blockDim.x + threadIdx.x;
    for (int i = tid; i < K * MO; i += MO * ROWS) Ws[i] = W[i];
    __syncthreads();
    int node = blockIdx.x * ROWS + threadIdx.y;
    if (node >= n) return;
    int o = threadIdx.x;
    const float* a = A + (size_t)node * K;
    float sum = 0.f;
#pragma unroll
    for (int k = 0; k < K; k += 4) {
        float4 av = *(const float4*)(a + k);
        sum += av.x * Ws[(k + 0) * MO + o] + av.y * Ws[(k + 1) * MO + o]
             + av.z * Ws[(k + 2) * MO + o] + av.w * Ws[(k + 3) * MO + o];
    }
    C[(size_t)node * MO + o] = sum;
}

// ---------------- GCN: chunked shuffle-broadcast gather ----------------
__global__ void k_gcn(const float* __restrict__ b1) {
    int n = blockIdx.x * 8 + (threadIdx.x >> 5);
    int lane = threadIdx.x & 31;
    if (n >= NN) return;
    int beg = d_rowptr[n], end = d_rowptr[n + 1];
    float a0 = 0.f, a1 = 0.f;
    for (int base = beg; base < end; base += 32) {
        int i = base + lane;
        bool valid = i < end;
        int s = valid ? d_csrc[i] : 0;
        float w = valid ? d_dis[s] : 0.f;
        int cnt = min(32, end - base);
#pragma unroll 4
        for (int j = 0; j < cnt; j++) {
            int   sj = __shfl_sync(~0u, s, j);
            float wj = __shfl_sync(~0u, w, j);
            const float* h = d_hW + (size_t)sj * 64;
            a0 += wj * h[lane];
            a1 += wj * h[32 + lane];
        }
    }
    float dn = d_dis[n];
    const float* hn = d_hW + (size_t)n * 64;
    float o0 = fmaxf(dn * (a0 + dn * hn[lane])      + b1[lane],      0.f);
    float o1 = fmaxf(dn * (a1 + dn * hn[32 + lane]) + b1[32 + lane], 0.f);
    d_g1[(size_t)n * 64 + lane]      = o0;
    d_g1[(size_t)n * 64 + 32 + lane] = o1;
}

// ---------------- attention logits ----------------
__global__ void k_al2(const float* __restrict__ asrc, const float* __restrict__ adst) {
    int n = blockIdx.x * 8 + (threadIdx.x >> 5);
    int lane = threadIdx.x & 31;
    if (n >= NN) return;
    const float* h = d_h2 + (size_t)n * 128;
    float s0 = h[lane] * asrc[lane]           + h[32 + lane] * asrc[32 + lane];
    float s1 = h[64 + lane] * asrc[64 + lane] + h[96 + lane] * asrc[96 + lane];
    float t0 = h[lane] * adst[lane]           + h[32 + lane] * adst[32 + lane];
    float t1 = h[64 + lane] * adst[64 + lane] + h[96 + lane] * adst[96 + lane];
#pragma unroll
    for (int off = 16; off; off >>= 1) {
        s0 += __shfl_xor_sync(~0u, s0, off);
        s1 += __shfl_xor_sync(~0u, s1, off);
        t0 += __shfl_xor_sync(~0u, t0, off);
        t1 += __shfl_xor_sync(~0u, t1, off);
    }
    if (lane == 0) {
        d_als2[n * 2] = s0; d_als2[n * 2 + 1] = s1;
        d_ald2[n * 2] = t0; d_ald2[n * 2 + 1] = t1;
    }
}

__global__ void k_al3(const float* __restrict__ asrc, const float* __restrict__ adst) {
    int n = blockIdx.x * 8 + (threadIdx.x >> 5);
    int lane = threadIdx.x & 31;
    if (n >= NN) return;
    const float* h = d_h3 + (size_t)n * 64;
    float s0 = h[lane] * asrc[lane] + h[32 + lane] * asrc[32 + lane];
    float t0 = h[lane] * adst[lane] + h[32 + lane] * adst[32 + lane];
#pragma unroll
    for (int off = 16; off; off >>= 1) {
        s0 += __shfl_xor_sync(~0u, s0, off);
        t0 += __shfl_xor_sync(~0u, t0, off);
    }
    if (lane == 0) { d_als3[n] = s0; d_ald3[n] = t0; }
}

// ---------------- GAT2: single-pass online softmax, chunked broadcast ----------------
__global__ void k_gat2(const float* __restrict__ b2) {
    int n = blockIdx.x * 8 + (threadIdx.x >> 5);
    int lane = threadIdx.x & 31;
    if (n >= NN) return;
    int beg = d_rowptr[n], end = d_rowptr[n + 1];
    float2 ald = *(const float2*)(d_ald2 + n * 2);
    float2 as  = *(const float2*)(d_als2 + n * 2);
    float m0 = lrelu(as.x + ald.x);     // self-loop seeds the max
    float m1 = lrelu(as.y + ald.y);
    const float* hn = d_h2 + (size_t)n * 128;
    float acc0 = hn[lane], acc1 = hn[32 + lane];     // self contribution (x=1)
    float acc2 = hn[64 + lane], acc3 = hn[96 + lane];
    float den0 = 1.f, den1 = 1.f;
    for (int base = beg; base < end; base += 32) {
        int i = base + lane;
        bool valid = i < end;
        int s = valid ? d_csrc[i] : 0;
        float e0 = -1e30f, e1 = -1e30f;
        if (valid) {
            float2 a = *(const float2*)(d_als2 + s * 2);
            e0 = lrelu(a.x + ald.x);
            e1 = lrelu(a.y + ald.y);
        }
        float cm0 = wmax(e0), cm1 = wmax(e1);
        if (cm0 > m0) { float r = __expf(m0 - cm0); acc0 *= r; acc1 *= r; den0 *= r; m0 = cm0; }
        if (cm1 > m1) { float r = __expf(m1 - cm1); acc2 *= r; acc3 *= r; den1 *= r; m1 = cm1; }
        float x0 = __expf(e0 - m0);     // 0 for invalid lanes
        float x1 = __expf(e1 - m1);
        den0 += wsum(x0);
        den1 += wsum(x1);
        int cnt = min(32, end - base);
#pragma unroll 4
        for (int j = 0; j < cnt; j++) {
            int   sj = __shfl_sync(~0u, s, j);
            float xa = __shfl_sync(~0u, x0, j);
            float xb = __shfl_sync(~0u, x1, j);
            const float* h = d_h2 + (size_t)sj * 128;
            acc0 += xa * h[lane];
            acc1 += xa * h[32 + lane];
            acc2 += xb * h[64 + lane];
            acc3 += xb * h[96 + lane];
        }
    }
    float i0 = 1.f / den0, i1 = 1.f / den1;
    float* g = d_g2 + (size_t)n * 128;
    g[lane]      = fmaxf(acc0 * i0 + b2[lane],      0.f);
    g[32 + lane] = fmaxf(acc1 * i0 + b2[32 + lane], 0.f);
    g[64 + lane] = fmaxf(acc2 * i1 + b2[64 + lane], 0.f);
    g[96 + lane] = fmaxf(acc3 * i1 + b2[96 + lane], 0.f);
}

// ---------------- GAT3: single-pass online softmax + pool scatter ----------------
__global__ void k_gat3pool(const float* __restrict__ b3) {
    int n = blockIdx.x * 8 + (threadIdx.x >> 5);
    int lane = threadIdx.x & 31;
    if (n >= NN) return;
    int beg = d_rowptr[n], end = d_rowptr[n + 1];
    float ald = d_ald3[n];
    float m = lrelu(d_als3[n] + ald);
    const float* hn = d_h3 + (size_t)n * 64;
    float acc0 = hn[lane], acc1 = hn[32 + lane];
    float den = 1.f;
    for (int base = beg; base < end; base += 32) {
        int i = base + lane;
        bool valid = i < end;
        int s = valid ? d_csrc[i] : 0;
        float e = valid ? lrelu(d_als3[s] + ald) : -1e30f;
        float cm = wmax(e);
        if (cm > m) { float r = __expf(m - cm); acc0 *= r; acc1 *= r; den *= r; m = cm; }
        float x = __expf(e - m);
        den += wsum(x);
        int cnt = min(32, end - base);
#pragma unroll 4
        for (int j = 0; j < cnt; j++) {
            int   sj = __shfl_sync(~0u, s, j);
            float xj = __shfl_sync(~0u, x, j);
            const float* h = d_h3 + (size_t)sj * 64;
            acc0 += xj * h[lane];
            acc1 += xj * h[32 + lane];
        }
    }
    float inv = 1.f / den;
    float o0 = acc0 * inv + b3[lane];
    float o1 = acc1 * inv + b3[32 + lane];
    int g = d_bat[n];
    atomicAdd(&d_pool[(size_t)g * 64 + lane],      o0);
    atomicAdd(&d_pool[(size_t)g * 64 + 32 + lane], o1);
    if (lane == 0) atomicAdd(&d_cnt[g], 1.0f);
}

__global__ void k_final(const float* __restrict__ Wfc, const float* __restrict__ bfc,
                        float* __restrict__ out) {
    int g = blockIdx.x * blockDim.x + threadIdx.x;
    if (g >= NG) return;
    float inv = 1.f / fmaxf(d_cnt[g], 1.f);
    float l0 = bfc[0], l1 = bfc[1];
#pragma unroll
    for (int f = 0; f < OUTC; f++) {
        float p = d_pool[g * OUTC + f] * inv;
        l0 += p * Wfc[f * 2 + 0];
        l1 += p * Wfc[f * 2 + 1];
    }
    float m = fmaxf(l0, l1);
    float lse = m + logf(expf(l0 - m) + expf(l1 - m));
    out[g * 2 + 0] = l0 - lse;
    out[g * 2 + 1] = l1 - lse;
}

// ---------------- host ----------------
extern "C" void kernel_launch(void* const* d_in, const int* in_sizes, int n_in,
                              void* d_out, int out_size) {
    const float* x    = (const float*)d_in[0];
    const void*  ei   = d_in[1];
    const void*  bat  = d_in[2];
    const float* W1   = (const float*)d_in[3];
    const float* b1   = (const float*)d_in[4];
    const float* W2   = (const float*)d_in[5];
    const float* as2  = (const float*)d_in[6];
    const float* ad2  = (const float*)d_in[7];
    const float* b2   = (const float*)d_in[8];
    const float* W3   = (const float*)d_in[9];
    const float* as3  = (const float*)d_in[10];
    const float* ad3  = (const float*)d_in[11];
    const float* b3   = (const float*)d_in[12];
    const float* Wfc  = (const float*)d_in[13];
    const float* bfc  = (const float*)d_in[14];
    float* out = (float*)d_out;

    void *p_hW, *p_g1, *p_g2, *p_h2, *p_h3;
    cudaGetSymbolAddress(&p_hW, d_hW);
    cudaGetSymbolAddress(&p_g1, d_g1);
    cudaGetSymbolAddress(&p_h2, d_h2);
    cudaGetSymbolAddress(&p_g2, d_g2);
    cudaGetSymbolAddress(&p_h3, d_h3);

    // indices + CSR build
    k_detect<<<1, 32>>>((const unsigned*)ei);
    k_zero0<<<(NN + 255) / 256, 256>>>();
    k_convert<<<(EE + 255) / 256, 256>>>(ei, bat);
    k_blocksum<<<NSB, SCB>>>();
    k_scanpart<<<1, SCB>>>();
    k_rowptr<<<NSB, SCB>>>();
    k_scatter<<<(EE + 255) / 256, 256>>>();

    // GCN
    k_gemm<128, 64, 4><<<(NN + 3) / 4, dim3(64, 4)>>>(x, W1, (float*)p_hW, NN);
    k_gcn<<<(NN + 7) / 8, 256>>>(b1);

    // GAT layer 2 (2 heads, concat)
    k_gemm<64, 128, 2><<<(NN + 1) / 2, dim3(128, 2)>>>((const float*)p_g1, W2, (float*)p_h2, NN);
    k_al2<<<(NN + 7) / 8, 256>>>(as2, ad2);
    k_gat2<<<(NN + 7) / 8, 256>>>(b2);

    // GAT layer 3 (1 head, mean over 1 head = identity)
    k_gemm<128, 64, 4><<<(NN + 3) / 4, dim3(64, 4)>>>((const float*)p_g2, W3, (float*)p_h3, NN);
    k_al3<<<(NN + 7) / 8, 256>>>(as3, ad3);
    k_gat3pool<<<(NN + 7) / 8, 256>>>(b3);

    // pooled @ Wfc + log_softmax
    k_final<<<(NG + 255) / 256, 256>>>(Wfc, bfc, out);
}

// round 15
// speedup vs baseline: 3.7496x; 2.1491x over previous
#include <cuda_runtime.h>
#include <cstdint>

#define NN   50000
#define EE   800000
#define FIN  128
#define HID  64
#define OUTC 64
#define NG   512

#define SCB  256
#define NSB  ((NN + SCB - 1) / SCB)

// ---------------- scratch ----------------
__device__ __align__(16) float d_hW  [NN * HID];
__device__ __align__(16) float d_dis [NN];
__device__ __align__(16) float d_g1  [NN * HID];
__device__ __align__(16) float d_h2  [NN * 2 * HID];
__device__ __align__(16) float d_als2[NN * 2];
__device__ __align__(16) float d_ald2[NN * 2];
__device__ __align__(16) float d_g2  [NN * 2 * HID];
__device__ __align__(16) float d_h3  [NN * OUTC];
__device__ __align__(16) float d_als3[NN];
__device__ __align__(16) float d_ald3[NN];
__device__ __align__(16) float d_pool[NG * OUTC];
__device__ __align__(16) float d_cnt [NG];

__device__ int d_fmt;
__device__ int d_src [EE];
__device__ int d_dstA[EE];
__device__ int d_bat [NN];
__device__ int d_rowptr[NN + 1];
__device__ int d_cursor[NN];
__device__ int d_csrc[EE];
__device__ int d_part[NSB];

// ---------------- helpers ----------------
__device__ __forceinline__ float lrelu(float x) { return x > 0.f ? x : 0.2f * x; }
__device__ __forceinline__ float wmax(float v) {
#pragma unroll
    for (int off = 16; off; off >>= 1) v = fmaxf(v, __shfl_xor_sync(~0u, v, off));
    return v;
}
__device__ __forceinline__ float wsum(float v) {
#pragma unroll
    for (int off = 16; off; off >>= 1) v += __shfl_xor_sync(~0u, v, off);
    return v;
}

// ---------------- index detection + conversion ----------------
__global__ void k_detect(const unsigned* __restrict__ ei_words) {
    int t = threadIdx.x;
    unsigned v = 0;
#pragma unroll
    for (int i = 0; i < 8; i++) v |= ei_words[2 * (t + 32 * i) + 1];
    unsigned any = __ballot_sync(~0u, v != 0u);
    if (t == 0) d_fmt = (any == 0u) ? 1 : 0;
}

__global__ void k_zero0() {
    int i = blockIdx.x * blockDim.x + threadIdx.x;
    if (i < NN) d_cursor[i] = 0;
    if (i < NG) d_cnt[i] = 0.f;
    if (i < NG * OUTC / 4) ((float4*)d_pool)[i] = make_float4(0.f, 0.f, 0.f, 0.f);
}

__global__ void k_convert(const void* __restrict__ ei, const void* __restrict__ bat) {
    int i = blockIdx.x * blockDim.x + threadIdx.x;
    int fmt = d_fmt;
    if (i < EE) {
        int s, d;
        if (fmt) {
            s = (int)((const long long*)ei)[i];
            d = (int)((const long long*)ei)[EE + i];
        } else {
            s = ((const int*)ei)[i];
            d = ((const int*)ei)[EE + i];
        }
        d_src [i] = s;
        d_dstA[i] = d;
        atomicAdd(&d_cursor[d], 1);
    }
    if (i < NN)
        d_bat[i] = fmt ? (int)((const long long*)bat)[i] : ((const int*)bat)[i];
}

// ---- parallel exclusive scan (3 phases) ----
__global__ void k_blocksum() {
    __shared__ int sh[SCB];
    int t = threadIdx.x, n = blockIdx.x * SCB + t;
    int c = (n < NN) ? d_cursor[n] : 0;
    sh[t] = c;
    __syncthreads();
#pragma unroll
    for (int off = SCB / 2; off; off >>= 1) {
        if (t < off) sh[t] += sh[t + off];
        __syncthreads();
    }
    if (t == 0) d_part[blockIdx.x] = sh[0];
}

__global__ void k_scanpart() {
    __shared__ int sh[SCB];
    int t = threadIdx.x;
    int v = (t < NSB) ? d_part[t] : 0;
    sh[t] = v;
    __syncthreads();
#pragma unroll
    for (int off = 1; off < SCB; off <<= 1) {
        int u = sh[t];
        int add = (t >= off) ? sh[t - off] : 0;
        __syncthreads();
        sh[t] = u + add;
        __syncthreads();
    }
    if (t < NSB) d_part[t] = sh[t] - v;
}

__global__ void k_rowptr() {
    __shared__ int sh[SCB];
    int t = threadIdx.x, n = blockIdx.x * SCB + t;
    int c = (n < NN) ? d_cursor[n] : 0;
    sh[t] = c;
    __syncthreads();
#pragma unroll
    for (int off = 1; off < SCB; off <<= 1) {
        int u = sh[t];
        int add = (t >= off) ? sh[t - off] : 0;
        __syncthreads();
        sh[t] = u + add;
        __syncthreads();
    }
    if (n < NN) {
        d_rowptr[n] = d_part[blockIdx.x] + sh[t] - c;
        d_dis[n] = rsqrtf((float)(c + 1));
        d_cursor[n] = 0;
        if (n == NN - 1) d_rowptr[NN] = EE;
    }
}

__global__ void k_scatter() {
    int e = blockIdx.x * blockDim.x + threadIdx.x;
    if (e >= EE) return;
    int d = d_dstA[e];
    int slot = d_rowptr[d] + atomicAdd(&d_cursor[d], 1);
    d_csrc[slot] = d_src[e];
}

// ---------------- register-blocked GEMM: C[n, MO] = A[n, K] @ W[K, MO] ----------------
// 256 threads; thread tile = 4 nodes x 4 outputs; W in smem, A via broadcast LDG.128
template<int K, int MO>
__global__ void k_gemm2(const float* __restrict__ A, const float* __restrict__ W,
                        float* __restrict__ C, int n) {
    constexpr int TX = MO / 4;        // threads across outputs (16 or 32)
    constexpr int TY = 256 / TX;      // thread groups across nodes
    constexpr int NPB = TY * 4;       // nodes per block
    __shared__ float Ws[K * MO];
    int tid = threadIdx.x;
    for (int i = tid; i < K * MO / 4; i += 256)
        ((float4*)Ws)[i] = ((const float4*)W)[i];
    __syncthreads();

    int tx = tid % TX, ty = tid / TX;
    int n0 = blockIdx.x * NPB + ty * 4;
    const float* Ar[4];
    bool valid[4];
#pragma unroll
    for (int r = 0; r < 4; r++) {
        int node = n0 + r;
        valid[r] = node < n;
        Ar[r] = A + (size_t)(valid[r] ? node : 0) * K;
    }
    float4 acc[4] = {};
#pragma unroll
    for (int k0 = 0; k0 < K; k0 += 4) {
        float4 w0 = *(const float4*)&Ws[(k0 + 0) * MO + tx * 4];
        float4 w1 = *(const float4*)&Ws[(k0 + 1) * MO + tx * 4];
        float4 w2 = *(const float4*)&Ws[(k0 + 2) * MO + tx * 4];
        float4 w3 = *(const float4*)&Ws[(k0 + 3) * MO + tx * 4];
#pragma unroll
        for (int r = 0; r < 4; r++) {
            float4 a = *(const float4*)(Ar[r] + k0);
            acc[r].x += a.x * w0.x + a.y * w1.x + a.z * w2.x + a.w * w3.x;
            acc[r].y += a.x * w0.y + a.y * w1.y + a.z * w2.y + a.w * w3.y;
            acc[r].z += a.x * w0.z + a.y * w1.z + a.z * w2.z + a.w * w3.z;
            acc[r].w += a.x * w0.w + a.y * w1.w + a.z * w2.w + a.w * w3.w;
        }
    }
#pragma unroll
    for (int r = 0; r < 4; r++)
        if (valid[r])
            *(float4*)&C[(size_t)(n0 + r) * MO + tx * 4] = acc[r];
}

// ---------------- GCN: float2-vectorized chunked broadcast gather ----------------
__global__ void k_gcn(const float* __restrict__ b1) {
    int n = blockIdx.x * 8 + (threadIdx.x >> 5);
    int lane = threadIdx.x & 31;
    if (n >= NN) return;
    int beg = d_rowptr[n], end = d_rowptr[n + 1];
    float2 acc = make_float2(0.f, 0.f);
    for (int base = beg; base < end; base += 32) {
        int i = base + lane;
        bool v = i < end;
        int s = v ? d_csrc[i] : 0;
        float w = v ? d_dis[s] : 0.f;
        int cnt = min(32, end - base);
#pragma unroll 8
        for (int j = 0; j < cnt; j++) {
            int   sj = __shfl_sync(~0u, s, j);
            float wj = __shfl_sync(~0u, w, j);
            float2 h = ((const float2*)(d_hW + (size_t)sj * 64))[lane];
            acc.x += wj * h.x;
            acc.y += wj * h.y;
        }
    }
    float dn = d_dis[n];
    float2 hn = ((const float2*)(d_hW + (size_t)n * 64))[lane];
    float2 b = ((const float2*)b1)[lane];
    float2 o;
    o.x = fmaxf(dn * (acc.x + dn * hn.x) + b.x, 0.f);
    o.y = fmaxf(dn * (acc.y + dn * hn.y) + b.y, 0.f);
    ((float2*)(d_g1 + (size_t)n * 64))[lane] = o;
}

// ---------------- attention logits ----------------
__global__ void k_al2(const float* __restrict__ asrc, const float* __restrict__ adst) {
    int n = blockIdx.x * 8 + (threadIdx.x >> 5);
    int lane = threadIdx.x & 31;
    if (n >= NN) return;
    const float* h = d_h2 + (size_t)n * 128;
    float s0 = h[lane] * asrc[lane]           + h[32 + lane] * asrc[32 + lane];
    float s1 = h[64 + lane] * asrc[64 + lane] + h[96 + lane] * asrc[96 + lane];
    float t0 = h[lane] * adst[lane]           + h[32 + lane] * adst[32 + lane];
    float t1 = h[64 + lane] * adst[64 + lane] + h[96 + lane] * adst[96 + lane];
#pragma unroll
    for (int off = 16; off; off >>= 1) {
        s0 += __shfl_xor_sync(~0u, s0, off);
        s1 += __shfl_xor_sync(~0u, s1, off);
        t0 += __shfl_xor_sync(~0u, t0, off);
        t1 += __shfl_xor_sync(~0u, t1, off);
    }
    if (lane == 0) {
        d_als2[n * 2] = s0; d_als2[n * 2 + 1] = s1;
        d_ald2[n * 2] = t0; d_ald2[n * 2 + 1] = t1;
    }
}

__global__ void k_al3(const float* __restrict__ asrc, const float* __restrict__ adst) {
    int n = blockIdx.x * 8 + (threadIdx.x >> 5);
    int lane = threadIdx.x & 31;
    if (n >= NN) return;
    const float* h = d_h3 + (size_t)n * 64;
    float s0 = h[lane] * asrc[lane] + h[32 + lane] * asrc[32 + lane];
    float t0 = h[lane] * adst[lane] + h[32 + lane] * adst[32 + lane];
#pragma unroll
    for (int off = 16; off; off >>= 1) {
        s0 += __shfl_xor_sync(~0u, s0, off);
        t0 += __shfl_xor_sync(~0u, t0, off);
    }
    if (lane == 0) { d_als3[n] = s0; d_ald3[n] = t0; }
}

// ---------------- GAT2: float4 rows, lane<16 = head0 / lane>=16 = head1 ----------------
__global__ void k_gat2(const float* __restrict__ b2) {
    int n = blockIdx.x * 8 + (threadIdx.x >> 5);
    int lane = threadIdx.x & 31;
    if (n >= NN) return;
    bool h0 = lane < 16;
    int beg = d_rowptr[n], end = d_rowptr[n + 1];
    float2 ald = *(const float2*)(d_ald2 + n * 2);
    float2 as  = *(const float2*)(d_als2 + n * 2);
    float m0 = lrelu(as.x + ald.x);
    float m1 = lrelu(as.y + ald.y);
    float4 acc = ((const float4*)(d_h2 + (size_t)n * 128))[lane];   // self (x=1)
    float den0 = 1.f, den1 = 1.f;
    for (int base = beg; base < end; base += 32) {
        int i = base + lane;
        bool v = i < end;
        int s = v ? d_csrc[i] : 0;
        float e0 = -1e30f, e1 = -1e30f;
        if (v) {
            float2 a = *(const float2*)(d_als2 + s * 2);
            e0 = lrelu(a.x + ald.x);
            e1 = lrelu(a.y + ald.y);
        }
        float cm0 = wmax(e0), cm1 = wmax(e1);
        if (cm0 > m0 || cm1 > m1) {
            float r0 = 1.f, r1 = 1.f;
            if (cm0 > m0) { r0 = __expf(m0 - cm0); den0 *= r0; m0 = cm0; }
            if (cm1 > m1) { r1 = __expf(m1 - cm1); den1 *= r1; m1 = cm1; }
            float rs = h0 ? r0 : r1;
            acc.x *= rs; acc.y *= rs; acc.z *= rs; acc.w *= rs;
        }
        float x0 = __expf(e0 - m0);
        float x1 = __expf(e1 - m1);
        den0 += wsum(x0);
        den1 += wsum(x1);
        int cnt = min(32, end - base);
#pragma unroll 8
        for (int j = 0; j < cnt; j++) {
            int   sj = __shfl_sync(~0u, s, j);
            float xa = __shfl_sync(~0u, x0, j);
            float xb = __shfl_sync(~0u, x1, j);
            float xs = h0 ? xa : xb;
            float4 h = ((const float4*)(d_h2 + (size_t)sj * 128))[lane];
            acc.x += xs * h.x;
            acc.y += xs * h.y;
            acc.z += xs * h.z;
            acc.w += xs * h.w;
        }
    }
    float inv = h0 ? (1.f / den0) : (1.f / den1);
    float4 b = ((const float4*)b2)[lane];
    float4 o;
    o.x = fmaxf(acc.x * inv + b.x, 0.f);
    o.y = fmaxf(acc.y * inv + b.y, 0.f);
    o.z = fmaxf(acc.z * inv + b.z, 0.f);
    o.w = fmaxf(acc.w * inv + b.w, 0.f);
    ((float4*)(d_g2 + (size_t)n * 128))[lane] = o;
}

// ---------------- GAT3: float2 rows + pool scatter ----------------
__global__ void k_gat3pool(const float* __restrict__ b3) {
    int n = blockIdx.x * 8 + (threadIdx.x >> 5);
    int lane = threadIdx.x & 31;
    if (n >= NN) return;
    int beg = d_rowptr[n], end = d_rowptr[n + 1];
    float ald = d_ald3[n];
    float m = lrelu(d_als3[n] + ald);
    float2 acc = ((const float2*)(d_h3 + (size_t)n * 64))[lane];    // self (x=1)
    float den = 1.f;
    for (int base = beg; base < end; base += 32) {
        int i = base + lane;
        bool v = i < end;
        int s = v ? d_csrc[i] : 0;
        float e = v ? lrelu(d_als3[s] + ald) : -1e30f;
        float cm = wmax(e);
        if (cm > m) { float r = __expf(m - cm); acc.x *= r; acc.y *= r; den *= r; m = cm; }
        float x = __expf(e - m);
        den += wsum(x);
        int cnt = min(32, end - base);
#pragma unroll 8
        for (int j = 0; j < cnt; j++) {
            int   sj = __shfl_sync(~0u, s, j);
            float xj = __shfl_sync(~0u, x, j);
            float2 h = ((const float2*)(d_h3 + (size_t)sj * 64))[lane];
            acc.x += xj * h.x;
            acc.y += xj * h.y;
        }
    }
    float inv = 1.f / den;
    float2 b = ((const float2*)b3)[lane];
    float o0 = acc.x * inv + b.x;
    float o1 = acc.y * inv + b.y;
    int g = d_bat[n];
    atomicAdd(&d_pool[(size_t)g * 64 + 2 * lane],     o0);
    atomicAdd(&d_pool[(size_t)g * 64 + 2 * lane + 1], o1);
    if (lane == 0) atomicAdd(&d_cnt[g], 1.0f);
}

__global__ void k_final(const float* __restrict__ Wfc, const float* __restrict__ bfc,
                        float* __restrict__ out) {
    int g = blockIdx.x * blockDim.x + threadIdx.x;
    if (g >= NG) return;
    float inv = 1.f / fmaxf(d_cnt[g], 1.f);
    float l0 = bfc[0], l1 = bfc[1];
#pragma unroll
    for (int f = 0; f < OUTC; f++) {
        float p = d_pool[g * OUTC + f] * inv;
        l0 += p * Wfc[f * 2 + 0];
        l1 += p * Wfc[f * 2 + 1];
    }
    float m = fmaxf(l0, l1);
    float lse = m + logf(expf(l0 - m) + expf(l1 - m));
    out[g * 2 + 0] = l0 - lse;
    out[g * 2 + 1] = l1 - lse;
}

// ---------------- host ----------------
extern "C" void kernel_launch(void* const* d_in, const int* in_sizes, int n_in,
                              void* d_out, int out_size) {
    const float* x    = (const float*)d_in[0];
    const void*  ei   = d_in[1];
    const void*  bat  = d_in[2];
    const float* W1   = (const float*)d_in[3];
    const float* b1   = (const float*)d_in[4];
    const float* W2   = (const float*)d_in[5];
    const float* as2  = (const float*)d_in[6];
    const float* ad2  = (const float*)d_in[7];
    const float* b2   = (const float*)d_in[8];
    const float* W3   = (const float*)d_in[9];
    const float* as3  = (const float*)d_in[10];
    const float* ad3  = (const float*)d_in[11];
    const float* b3   = (const float*)d_in[12];
    const float* Wfc  = (const float*)d_in[13];
    const float* bfc  = (const float*)d_in[14];
    float* out = (float*)d_out;

    void *p_hW, *p_g1, *p_g2, *p_h2, *p_h3;
    cudaGetSymbolAddress(&p_hW, d_hW);
    cudaGetSymbolAddress(&p_g1, d_g1);
    cudaGetSymbolAddress(&p_h2, d_h2);
    cudaGetSymbolAddress(&p_g2, d_g2);
    cudaGetSymbolAddress(&p_h3, d_h3);

    // indices + CSR build
    k_detect<<<1, 32>>>((const unsigned*)ei);
    k_zero0<<<(NN + 255) / 256, 256>>>();
    k_convert<<<(EE + 255) / 256, 256>>>(ei, bat);
    k_blocksum<<<NSB, SCB>>>();
    k_scanpart<<<1, SCB>>>();
    k_rowptr<<<NSB, SCB>>>();
    k_scatter<<<(EE + 255) / 256, 256>>>();

    // GCN: 64 nodes/block
    k_gemm2<128, 64><<<(NN + 63) / 64, 256>>>(x, W1, (float*)p_hW, NN);
    k_gcn<<<(NN + 7) / 8, 256>>>(b1);

    // GAT layer 2: 32 nodes/block
    k_gemm2<64, 128><<<(NN + 31) / 32, 256>>>((const float*)p_g1, W2, (float*)p_h2, NN);
    k_al2<<<(NN + 7) / 8, 256>>>(as2, ad2);
    k_gat2<<<(NN + 7) / 8, 256>>>(b2);

    // GAT layer 3: 64 nodes/block
    k_gemm2<128, 64><<<(NN + 63) / 64, 256>>>((const float*)p_g2, W3, (float*)p_h3, NN);
    k_al3<<<(NN + 7) / 8, 256>>>(as3, ad3);
    k_gat3pool<<<(NN + 7) / 8, 256>>>(b3);

    // pooled @ Wfc + log_softmax
    k_final<<<(NG + 255) / 256, 256>>>(Wfc, bfc, out);
}